// round 14
// baseline (speedup 1.0000x reference)
#include <cuda_runtime.h>

#define NP 60000
#define NM 30000
#define NN 90000
#define ETR 2000000
#define EDC 400000
#define NBINS (2*NN)
#define NBLK 176                         // scan blocks (176*1024 >= NBINS)
#define SCBLK ((ETR/8 + 255) / 256)      // 977 scatter blocks
#define TFBLK ((NN + 255) / 256)         // 352 transform blocks
#define PCBLK 24                         // precomp blocks
#define ZBLK  176                        // zero blocks

// ---------------- device scratch ---------------------------------------------
__device__ float4 g_bufA4[NN * 8];
__device__ float4 g_bufB4[NN * 8];
__device__ int    g_cnt[NBINS];
__device__ int    g_off[NBINS + 1];
__device__ int    g_cur[NBINS];
__device__ int    g_esrc[ETR];
__device__ float  g_Wall[4 * 2048];
__device__ volatile int g_blkAgg[NBLK];
__device__ volatile int g_blkFlag[NBLK];

// ---------------- hist -------------------------------------------------------
__global__ void k_hist(const int* __restrict__ ei, const int* __restrict__ et) {
    int t = blockIdx.x * blockDim.x + threadIdx.x;
    int e = t * 8;
    if (e >= ETR) return;
    int4 d0 = *(const int4*)&ei[ETR + e];
    int4 d1 = *(const int4*)&ei[ETR + e + 4];
    int4 r0 = *(const int4*)&et[e];
    int4 r1 = *(const int4*)&et[e + 4];
    atomicAdd(&g_cnt[d0.x * 2 + r0.x], 1);
    atomicAdd(&g_cnt[d0.y * 2 + r0.y], 1);
    atomicAdd(&g_cnt[d0.z * 2 + r0.z], 1);
    atomicAdd(&g_cnt[d0.w * 2 + r0.w], 1);
    atomicAdd(&g_cnt[d1.x * 2 + r1.x], 1);
    atomicAdd(&g_cnt[d1.y * 2 + r1.y], 1);
    atomicAdd(&g_cnt[d1.z * 2 + r1.z], 1);
    atomicAdd(&g_cnt[d1.w * 2 + r1.w], 1);
}

// ---------------- single-pass scan with decoupled lookback -------------------
__global__ __launch_bounds__(256)
void k_scanLB() {
    __shared__ int sh[256];
    int b = blockIdx.x, t = threadIdx.x;
    int base = b * 1024 + t * 4;
    int4 v = make_int4(0, 0, 0, 0);
    if (base < NBINS) v = *(const int4*)&g_cnt[base];
    int s = v.x + v.y + v.z + v.w;
    sh[t] = s;
    __syncthreads();
    for (int off = 1; off < 256; off <<= 1) {
        int tmp = (t >= off) ? sh[t - off] : 0;
        __syncthreads();
        sh[t] += tmp;
        __syncthreads();
    }
    int myinc = sh[t];
    if (t == 255) {
        g_blkAgg[b] = myinc;
        __threadfence();
        g_blkFlag[b] = 1;
    }
    int prev = 0;
    for (int j = t; j < b; j += 256) {
        while (g_blkFlag[j] == 0) { }
        prev += g_blkAgg[j];
    }
    __syncthreads();
    sh[t] = prev;
    __syncthreads();
    for (int off = 128; off >= 1; off >>= 1) {
        if (t < off) sh[t] += sh[t + off];
        __syncthreads();
    }
    int blkoff = sh[0];
    if (base < NBINS) {
        int run = myinc - s + blkoff;
        int4 o;
        o.x = run;           run += v.x;
        o.y = run;           run += v.y;
        o.z = run;           run += v.z;
        o.w = run;
        *(int4*)&g_off[base] = o;
        *(int4*)&g_cur[base] = o;
    }
    if (b == 0 && t == 0) g_off[NBINS] = ETR;
}

// ------- fused: scatter + input transform + basis precomp + state reset ------
__global__ __launch_bounds__(256)
void k_scatter_front(const int* __restrict__ ei, const int* __restrict__ et,
                     const float* __restrict__ xp, const float* __restrict__ xm,
                     const float* __restrict__ Wp, const float* __restrict__ bp,
                     const float* __restrict__ Wm, const float* __restrict__ bm,
                     const float* __restrict__ b1, const float* __restrict__ c1,
                     const float* __restrict__ b2, const float* __restrict__ c2,
                     const float* __restrict__ b3, const float* __restrict__ c3,
                     const float* __restrict__ b4, const float* __restrict__ c4) {
    int bx = blockIdx.x;
    int t = threadIdx.x;

    if (bx < SCBLK) {
        int e = (bx * 256 + t) * 8;
        if (e >= ETR) return;
        int4 s0 = *(const int4*)&ei[e];
        int4 s1 = *(const int4*)&ei[e + 4];
        int4 d0 = *(const int4*)&ei[ETR + e];
        int4 d1 = *(const int4*)&ei[ETR + e + 4];
        int4 r0 = *(const int4*)&et[e];
        int4 r1 = *(const int4*)&et[e + 4];
        int p0 = atomicAdd(&g_cur[d0.x * 2 + r0.x], 1);
        int p1 = atomicAdd(&g_cur[d0.y * 2 + r0.y], 1);
        int p2 = atomicAdd(&g_cur[d0.z * 2 + r0.z], 1);
        int p3 = atomicAdd(&g_cur[d0.w * 2 + r0.w], 1);
        int p4 = atomicAdd(&g_cur[d1.x * 2 + r1.x], 1);
        int p5 = atomicAdd(&g_cur[d1.y * 2 + r1.y], 1);
        int p6 = atomicAdd(&g_cur[d1.z * 2 + r1.z], 1);
        int p7 = atomicAdd(&g_cur[d1.w * 2 + r1.w], 1);
        g_esrc[p0] = s0.x; g_esrc[p1] = s0.y; g_esrc[p2] = s0.z; g_esrc[p3] = s0.w;
        g_esrc[p4] = s1.x; g_esrc[p5] = s1.y; g_esrc[p6] = s1.z; g_esrc[p7] = s1.w;
        return;
    }
    if (bx < SCBLK + TFBLK) {
        __shared__ float4 sWp[512], sWm[512];
        __shared__ float  sbp[16], sbm[16];
        for (int i = t; i < 512; i += 256) {
            sWp[i] = __ldg((const float4*)Wp + i);
            sWm[i] = __ldg((const float4*)Wm + i);
        }
        if (t < 16) { sbp[t] = __ldg(&bp[t]); sbm[t] = __ldg(&bm[t]); }
        __syncthreads();

        int n = (bx - SCBLK) * 256 + t;
        if (n >= NN) return;
        bool paper = (n < NP);
        const float4* xb = paper ? ((const float4*)xp + (long)n * 32)
                                 : ((const float4*)xm + (long)(n - NP) * 32);
        const float4* W  = paper ? sWp : sWm;
        const float*  sb = paper ? sbp : sbm;

        float acc[16];
#pragma unroll
        for (int o = 0; o < 16; o++) acc[o] = sb[o];
#pragma unroll
        for (int k8 = 0; k8 < 4; k8++) {
            float4 xv[8];
#pragma unroll
            for (int m = 0; m < 8; m++) xv[m] = __ldg(xb + k8 * 8 + m);
#pragma unroll
            for (int m = 0; m < 8; m++) {
                const float* xs = (const float*)&xv[m];
#pragma unroll
                for (int j = 0; j < 4; j++) {
                    int k = k8 * 32 + m * 4 + j;
                    float x = xs[j];
#pragma unroll
                    for (int o4 = 0; o4 < 4; o4++) {
                        float4 wv = W[k * 4 + o4];
                        acc[o4*4+0] += x * wv.x;
                        acc[o4*4+1] += x * wv.y;
                        acc[o4*4+2] += x * wv.z;
                        acc[o4*4+3] += x * wv.w;
                    }
                }
            }
        }
#pragma unroll
        for (int o4 = 0; o4 < 4; o4++)
            g_bufA4[n * 4 + o4] = make_float4(acc[o4*4+0], acc[o4*4+1],
                                              acc[o4*4+2], acc[o4*4+3]);
        return;
    }
    if (bx < SCBLK + TFBLK + PCBLK) {
        int tid = (bx - SCBLK - TFBLK) * 256 + t;
        const int sizes[4] = {512, 1024, 1024, 512};
        const float* bases[4] = {b1, b2, b3, b4};
        const float* comp[4]  = {c1, c2, c3, c4};
        if (tid >= 6144) return;
        int rem = tid;
        int l = 0;
        while (rem >= 2 * sizes[l]) { rem -= 2 * sizes[l]; l++; }
        int sz = sizes[l];
        int r = rem / sz;
        int io = rem - r * sz;
        float s = 0.f;
#pragma unroll
        for (int b = 0; b < 4; b++)
            s += __ldg(&comp[l][r * 4 + b]) * __ldg(&bases[l][b * sz + io]);
        g_Wall[l * 2048 + r * 1024 + io] = s;
        return;
    }
    {
        int zb = bx - SCBLK - TFBLK - PCBLK;
        int i = zb * 256 + t;
        if (i < NBINS / 4) *(int4*)&g_cnt[i * 4] = make_int4(0, 0, 0, 0);
        if (zb == 0 && t < NBLK) { g_blkFlag[t] = 0; g_blkAgg[t] = 0; }
    }
}

// ---------------- fused layer: gather-mean + combine -------------------------
// 64 nodes/block (128 bins). Gather: warp-cooperative, ONE bin at a time per
// warp (16 bins sequentially) -> per-warp time ~ sum of its bins, not max.
// Lanes = EL edge-lanes x CH chunks; idx loads coalesced; shfl reduction.
template <int INS, int OUTS>
__global__ __launch_bounds__(256, 4)
void k_layer(int inA, int layer,
             const float* __restrict__ root, const float* __restrict__ bias,
             int do_relu) {
    const int CH = INS / 4;              // float4 chunks per row
    const int EL = 32 / CH;              // edge lanes per bin
    const int NODES = 64, BINS = 128;
    const int APAD = 2 * INS + 2;
    __shared__ float sA[NODES * APAD];
    __shared__ alignas(16) float sR[INS * OUTS];
    __shared__ alignas(16) float sW0[INS * OUTS];
    __shared__ alignas(16) float sW1[INS * OUTS];
    __shared__ float sb[OUTS];

    int tid = threadIdx.x;
    const float* W0g = g_Wall + layer * 2048;
    const float* W1g = W0g + 1024;
    for (int i = tid; i < INS * OUTS; i += 256) {
        sR[i]  = __ldg(&root[i]);
        sW0[i] = W0g[i];
        sW1[i] = W1g[i];
    }
    if (tid < OUTS) sb[tid] = __ldg(&bias[tid]);

    int nodeBase = blockIdx.x * NODES;
    int bin0 = nodeBase * 2;
    const float4* __restrict__ xin = inA ? g_bufA4 : g_bufB4;
    float* __restrict__ xout = inA ? (float*)g_bufB4 : (float*)g_bufA4;

    // ---- gather phase: warp per bin, 16 bins per warp ----
    {
        int wid = tid >> 5;
        int lane = tid & 31;
        int el = lane >> (INS == 16 ? 2 : 3);   // lane / CH
        int c  = lane & (CH - 1);
        for (int bi = 0; bi < 16; bi++) {
            int w = bin0 + wid * 16 + bi;       // uniform across warp
            if (w >= NBINS) break;
            int start = __ldg(&g_off[w]);
            int cnt   = __ldg(&g_off[w + 1]) - start;
            float4 s0 = make_float4(0.f, 0.f, 0.f, 0.f), s1 = s0;
            int i = el;
            for (; i + EL < cnt; i += 2 * EL) {
                int a = __ldg(&g_esrc[start + i]);
                int b = __ldg(&g_esrc[start + i + EL]);
                float4 va = __ldg(xin + a * CH + c);
                float4 vb = __ldg(xin + b * CH + c);
                s0.x += va.x; s0.y += va.y; s0.z += va.z; s0.w += va.w;
                s1.x += vb.x; s1.y += vb.y; s1.z += vb.z; s1.w += vb.w;
            }
            if (i < cnt) {
                int a = __ldg(&g_esrc[start + i]);
                float4 va = __ldg(xin + a * CH + c);
                s0.x += va.x; s0.y += va.y; s0.z += va.z; s0.w += va.w;
            }
            s0.x += s1.x; s0.y += s1.y; s0.z += s1.z; s0.w += s1.w;
            // reduce across edge lanes (stride CH .. 16)
#pragma unroll
            for (int off = 16; off >= CH; off >>= 1) {
                s0.x += __shfl_xor_sync(0xffffffffu, s0.x, off);
                s0.y += __shfl_xor_sync(0xffffffffu, s0.y, off);
                s0.z += __shfl_xor_sync(0xffffffffu, s0.z, off);
                s0.w += __shfl_xor_sync(0xffffffffu, s0.w, off);
            }
            if (el == 0) {
                float inv = cnt > 0 ? 1.0f / (float)cnt : 0.0f;
                int bl = wid * 16 + bi;
                int node = bl >> 1, rel = bl & 1;
                int b = node * APAD + rel * INS + c * 4;
                sA[b]     = s0.x * inv;
                sA[b + 1] = s0.y * inv;
                sA[b + 2] = s0.z * inv;
                sA[b + 3] = s0.w * inv;
            }
        }
    }
    __syncthreads();

    // ---- combine phase: 1 node per 4 threads, q-th output quarter ----
    const int OQ = OUTS / 4;
    int node = tid >> 2;                 // 0..63
    int q = tid & 3;
    int o0 = q * OQ;
    int gn = nodeBase + node;
    if (gn >= NN) return;
    const float* A = sA + node * APAD;

    float acc[OQ];
#pragma unroll
    for (int j = 0; j < OQ; j++) acc[j] = sb[o0 + j];

#pragma unroll
    for (int i4 = 0; i4 < CH; i4++) {
        float4 xv4 = __ldg(xin + gn * CH + i4);
        const float* xs = (const float*)&xv4;
#pragma unroll
        for (int j = 0; j < 4; j++) {
            int i = i4 * 4 + j;
            float xv = xs[j];
            float a0 = A[i], a1 = A[INS + i];
            const float4* r4  = (const float4*)&sR[i * OUTS + o0];
            const float4* w04 = (const float4*)&sW0[i * OUTS + o0];
            const float4* w14 = (const float4*)&sW1[i * OUTS + o0];
#pragma unroll
            for (int j4 = 0; j4 < OQ / 4; j4++) {
                float4 r = r4[j4], w0 = w04[j4], w1 = w14[j4];
                acc[j4*4+0] += xv * r.x + a0 * w0.x + a1 * w1.x;
                acc[j4*4+1] += xv * r.y + a0 * w0.y + a1 * w1.y;
                acc[j4*4+2] += xv * r.z + a0 * w0.z + a1 * w1.z;
                acc[j4*4+3] += xv * r.w + a0 * w0.w + a1 * w1.w;
            }
        }
    }
    if (do_relu) {
#pragma unroll
        for (int j = 0; j < OQ; j++) acc[j] = fmaxf(acc[j], 0.f);
    }
#pragma unroll
    for (int j4 = 0; j4 < OQ / 4; j4++)
        ((float4*)xout)[gn * (OUTS / 4) + q * (OQ / 4) + j4] =
            make_float4(acc[j4*4+0], acc[j4*4+1], acc[j4*4+2], acc[j4*4+3]);
}

// ---------------- decoder ----------------------------------------------------
__global__ void k_decode(const int* __restrict__ pei, const int* __restrict__ pet,
                         const int* __restrict__ nei, const int* __restrict__ net,
                         const float* __restrict__ Wd0, const float* __restrict__ bd0,
                         const float* __restrict__ Wd1, const float* __restrict__ bd1,
                         float* __restrict__ out) {
    __shared__ float sW0[256], sW1[256], sb0[16], sb1[16];
    int tid = threadIdx.x;
    if (tid < 256) { sW0[tid] = Wd0[tid]; sW1[tid] = Wd1[tid]; }
    if (tid < 16) { sb0[tid] = bd0[tid]; sb1[tid] = bd1[tid]; }
    __syncthreads();
    int g = blockIdx.x * blockDim.x + tid;
    int e = g >> 4;
    int c = g & 15;
    if (e >= 2 * EDC) return;
    const int* ei;
    const int* et;
    int le;
    float* o;
    if (e < EDC) { ei = pei; et = pet; le = e; o = out; }
    else         { ei = nei; et = net; le = e - EDC; o = out + EDC; }
    const float* z = (const float*)g_bufA4;
    int src = __ldg(&ei[le]);
    int dst = __ldg(&ei[EDC + le]);
    int t = __ldg(&et[le]);
    float zs = __ldg(&z[src * 16 + c]);
    float zd = __ldg(&z[dst * 16 + c]);
    const float* W = (t == 0) ? sW0 : sW1;
    float h = (t == 0) ? sb0[c] : sb1[c];
#pragma unroll
    for (int i = 0; i < 16; i++) {
        float zi = __shfl_sync(0xffffffffu, zs, i, 16);
        h += zi * W[i * 16 + c];
    }
    float p = h * zd;
#pragma unroll
    for (int off = 8; off >= 1; off >>= 1)
        p += __shfl_down_sync(0xffffffffu, p, off, 16);
    if (c == 0) o[le] = p;
}

// ---------------- launch -----------------------------------------------------
extern "C" void kernel_launch(void* const* d_in, const int* in_sizes, int n_in,
                              void* d_out, int out_size) {
    const float* xp   = (const float*)d_in[0];
    const float* xm   = (const float*)d_in[1];
    const int*   tei  = (const int*)d_in[2];
    const int*   tet  = (const int*)d_in[3];
    const int*   pei  = (const int*)d_in[4];
    const int*   pet  = (const int*)d_in[5];
    const int*   nei  = (const int*)d_in[6];
    const int*   net_ = (const int*)d_in[7];
    const float* Wp   = (const float*)d_in[8];
    const float* bp   = (const float*)d_in[9];
    const float* Wm   = (const float*)d_in[10];
    const float* bm   = (const float*)d_in[11];
    const float* Wd0  = (const float*)d_in[12];
    const float* bd0  = (const float*)d_in[13];
    const float* Wd1  = (const float*)d_in[14];
    const float* bd1  = (const float*)d_in[15];
    const float* bases[4] = {(const float*)d_in[16], (const float*)d_in[20],
                             (const float*)d_in[24], (const float*)d_in[28]};
    const float* comp[4]  = {(const float*)d_in[17], (const float*)d_in[21],
                             (const float*)d_in[25], (const float*)d_in[29]};
    const float* root[4]  = {(const float*)d_in[18], (const float*)d_in[22],
                             (const float*)d_in[26], (const float*)d_in[30]};
    const float* bias[4]  = {(const float*)d_in[19], (const float*)d_in[23],
                             (const float*)d_in[27], (const float*)d_in[31]};
    float* out = (float*)d_out;

    const int TB = 256;
    // 1: hist, 2: scanLB, 3: fused front, 4: layer1 (PROFILED SLOT), 5-7: layers, 8: decode
    k_hist<<<(ETR / 8 + TB - 1) / TB, TB>>>(tei, tet);
    k_scanLB<<<NBLK, 256>>>();
    k_scatter_front<<<SCBLK + TFBLK + PCBLK + ZBLK, 256>>>(
        tei, tet, xp, xm, Wp, bp, Wm, bm,
        bases[0], comp[0], bases[1], comp[1],
        bases[2], comp[2], bases[3], comp[3]);

    const int LBLK = (NN + 63) / 64;   // 1407
    k_layer<16, 32><<<LBLK, 256>>>(1, 0, root[0], bias[0], 1);
    k_layer<32, 32><<<LBLK, 256>>>(0, 1, root[1], bias[1], 1);
    k_layer<32, 32><<<LBLK, 256>>>(1, 2, root[2], bias[2], 1);
    k_layer<32, 16><<<LBLK, 256>>>(0, 3, root[3], bias[3], 0);

    k_decode<<<(2 * EDC * 16 + TB - 1) / TB, TB>>>(pei, pet, nei, net_,
                                                   Wd0, bd0, Wd1, bd1, out);
}

// round 15
// speedup vs baseline: 1.4163x; 1.4163x over previous
#include <cuda_runtime.h>
#include <cuda_fp16.h>

#define NP 60000
#define NM 30000
#define NN 90000
#define ETR 2000000
#define EDC 400000
#define NBINS (2*NN)
#define NBLK 176                         // scan blocks (176*1024 >= NBINS)
#define SCBLK ((ETR/8 + 255) / 256)      // 977 scatter blocks
#define TFBLK ((NN + 255) / 256)         // 352 transform blocks
#define PCBLK 24                         // precomp blocks
#define ZBLK  176                        // zero blocks

// ---------------- device scratch ---------------------------------------------
__device__ float4 g_bufA4[NN * 8];
__device__ float4 g_bufB4[NN * 8];
__device__ __align__(16) __half g_hA[NN * 32];   // fp16 mirrors (gather path)
__device__ __align__(16) __half g_hB[NN * 32];
__device__ int    g_cnt[NBINS];
__device__ int    g_off[NBINS + 1];
__device__ int    g_cur[NBINS];
__device__ int    g_esrc[ETR];
__device__ float  g_Wall[4 * 2048];
__device__ volatile int g_blkAgg[NBLK];
__device__ volatile int g_blkFlag[NBLK];

// ---------------- hist -------------------------------------------------------
__global__ void k_hist(const int* __restrict__ ei, const int* __restrict__ et) {
    int t = blockIdx.x * blockDim.x + threadIdx.x;
    int e = t * 8;
    if (e >= ETR) return;
    int4 d0 = *(const int4*)&ei[ETR + e];
    int4 d1 = *(const int4*)&ei[ETR + e + 4];
    int4 r0 = *(const int4*)&et[e];
    int4 r1 = *(const int4*)&et[e + 4];
    atomicAdd(&g_cnt[d0.x * 2 + r0.x], 1);
    atomicAdd(&g_cnt[d0.y * 2 + r0.y], 1);
    atomicAdd(&g_cnt[d0.z * 2 + r0.z], 1);
    atomicAdd(&g_cnt[d0.w * 2 + r0.w], 1);
    atomicAdd(&g_cnt[d1.x * 2 + r1.x], 1);
    atomicAdd(&g_cnt[d1.y * 2 + r1.y], 1);
    atomicAdd(&g_cnt[d1.z * 2 + r1.z], 1);
    atomicAdd(&g_cnt[d1.w * 2 + r1.w], 1);
}

// ---------------- single-pass scan with decoupled lookback -------------------
__global__ __launch_bounds__(256)
void k_scanLB() {
    __shared__ int sh[256];
    int b = blockIdx.x, t = threadIdx.x;
    int base = b * 1024 + t * 4;
    int4 v = make_int4(0, 0, 0, 0);
    if (base < NBINS) v = *(const int4*)&g_cnt[base];
    int s = v.x + v.y + v.z + v.w;
    sh[t] = s;
    __syncthreads();
    for (int off = 1; off < 256; off <<= 1) {
        int tmp = (t >= off) ? sh[t - off] : 0;
        __syncthreads();
        sh[t] += tmp;
        __syncthreads();
    }
    int myinc = sh[t];
    if (t == 255) {
        g_blkAgg[b] = myinc;
        __threadfence();
        g_blkFlag[b] = 1;
    }
    int prev = 0;
    for (int j = t; j < b; j += 256) {
        while (g_blkFlag[j] == 0) { }
        prev += g_blkAgg[j];
    }
    __syncthreads();
    sh[t] = prev;
    __syncthreads();
    for (int off = 128; off >= 1; off >>= 1) {
        if (t < off) sh[t] += sh[t + off];
        __syncthreads();
    }
    int blkoff = sh[0];
    if (base < NBINS) {
        int run = myinc - s + blkoff;
        int4 o;
        o.x = run;           run += v.x;
        o.y = run;           run += v.y;
        o.z = run;           run += v.z;
        o.w = run;
        *(int4*)&g_off[base] = o;
        *(int4*)&g_cur[base] = o;
    }
    if (b == 0 && t == 0) g_off[NBINS] = ETR;
}

// ------- fused: scatter + input transform + basis precomp + state reset ------
__global__ __launch_bounds__(256)
void k_scatter_front(const int* __restrict__ ei, const int* __restrict__ et,
                     const float* __restrict__ xp, const float* __restrict__ xm,
                     const float* __restrict__ Wp, const float* __restrict__ bp,
                     const float* __restrict__ Wm, const float* __restrict__ bm,
                     const float* __restrict__ b1, const float* __restrict__ c1,
                     const float* __restrict__ b2, const float* __restrict__ c2,
                     const float* __restrict__ b3, const float* __restrict__ c3,
                     const float* __restrict__ b4, const float* __restrict__ c4) {
    int bx = blockIdx.x;
    int t = threadIdx.x;

    if (bx < SCBLK) {
        int e = (bx * 256 + t) * 8;
        if (e >= ETR) return;
        int4 s0 = *(const int4*)&ei[e];
        int4 s1 = *(const int4*)&ei[e + 4];
        int4 d0 = *(const int4*)&ei[ETR + e];
        int4 d1 = *(const int4*)&ei[ETR + e + 4];
        int4 r0 = *(const int4*)&et[e];
        int4 r1 = *(const int4*)&et[e + 4];
        int p0 = atomicAdd(&g_cur[d0.x * 2 + r0.x], 1);
        int p1 = atomicAdd(&g_cur[d0.y * 2 + r0.y], 1);
        int p2 = atomicAdd(&g_cur[d0.z * 2 + r0.z], 1);
        int p3 = atomicAdd(&g_cur[d0.w * 2 + r0.w], 1);
        int p4 = atomicAdd(&g_cur[d1.x * 2 + r1.x], 1);
        int p5 = atomicAdd(&g_cur[d1.y * 2 + r1.y], 1);
        int p6 = atomicAdd(&g_cur[d1.z * 2 + r1.z], 1);
        int p7 = atomicAdd(&g_cur[d1.w * 2 + r1.w], 1);
        g_esrc[p0] = s0.x; g_esrc[p1] = s0.y; g_esrc[p2] = s0.z; g_esrc[p3] = s0.w;
        g_esrc[p4] = s1.x; g_esrc[p5] = s1.y; g_esrc[p6] = s1.z; g_esrc[p7] = s1.w;
        return;
    }
    if (bx < SCBLK + TFBLK) {
        __shared__ float4 sWp[512], sWm[512];
        __shared__ float  sbp[16], sbm[16];
        for (int i = t; i < 512; i += 256) {
            sWp[i] = __ldg((const float4*)Wp + i);
            sWm[i] = __ldg((const float4*)Wm + i);
        }
        if (t < 16) { sbp[t] = __ldg(&bp[t]); sbm[t] = __ldg(&bm[t]); }
        __syncthreads();

        int n = (bx - SCBLK) * 256 + t;
        if (n >= NN) return;
        bool paper = (n < NP);
        const float4* xb = paper ? ((const float4*)xp + (long)n * 32)
                                 : ((const float4*)xm + (long)(n - NP) * 32);
        const float4* W  = paper ? sWp : sWm;
        const float*  sb = paper ? sbp : sbm;

        float acc[16];
#pragma unroll
        for (int o = 0; o < 16; o++) acc[o] = sb[o];
#pragma unroll
        for (int k8 = 0; k8 < 4; k8++) {
            float4 xv[8];
#pragma unroll
            for (int m = 0; m < 8; m++) xv[m] = __ldg(xb + k8 * 8 + m);
#pragma unroll
            for (int m = 0; m < 8; m++) {
                const float* xs = (const float*)&xv[m];
#pragma unroll
                for (int j = 0; j < 4; j++) {
                    int k = k8 * 32 + m * 4 + j;
                    float x = xs[j];
#pragma unroll
                    for (int o4 = 0; o4 < 4; o4++) {
                        float4 wv = W[k * 4 + o4];
                        acc[o4*4+0] += x * wv.x;
                        acc[o4*4+1] += x * wv.y;
                        acc[o4*4+2] += x * wv.z;
                        acc[o4*4+3] += x * wv.w;
                    }
                }
            }
        }
#pragma unroll
        for (int o4 = 0; o4 < 4; o4++)
            g_bufA4[n * 4 + o4] = make_float4(acc[o4*4+0], acc[o4*4+1],
                                              acc[o4*4+2], acc[o4*4+3]);
        // fp16 mirror (row = 16 halves = 32B)
        {
            uint4 hv[2];
            __half2* hp = (__half2*)hv;
#pragma unroll
            for (int o2 = 0; o2 < 8; o2++)
                hp[o2] = __floats2half2_rn(acc[o2 * 2], acc[o2 * 2 + 1]);
            ((uint4*)g_hA)[n * 2 + 0] = hv[0];
            ((uint4*)g_hA)[n * 2 + 1] = hv[1];
        }
        return;
    }
    if (bx < SCBLK + TFBLK + PCBLK) {
        int tid = (bx - SCBLK - TFBLK) * 256 + t;
        const int sizes[4] = {512, 1024, 1024, 512};
        const float* bases[4] = {b1, b2, b3, b4};
        const float* comp[4]  = {c1, c2, c3, c4};
        if (tid >= 6144) return;
        int rem = tid;
        int l = 0;
        while (rem >= 2 * sizes[l]) { rem -= 2 * sizes[l]; l++; }
        int sz = sizes[l];
        int r = rem / sz;
        int io = rem - r * sz;
        float s = 0.f;
#pragma unroll
        for (int b = 0; b < 4; b++)
            s += __ldg(&comp[l][r * 4 + b]) * __ldg(&bases[l][b * sz + io]);
        g_Wall[l * 2048 + r * 1024 + io] = s;
        return;
    }
    {
        int zb = bx - SCBLK - TFBLK - PCBLK;
        int i = zb * 256 + t;
        if (i < NBINS / 4) *(int4*)&g_cnt[i * 4] = make_int4(0, 0, 0, 0);
        if (zb == 0 && t < NBLK) { g_blkFlag[t] = 0; g_blkAgg[t] = 0; }
    }
}

// ---------------- fused layer: gather-mean (fp16 rows) + combine (fp32) ------
// R10 champion structure: 128 nodes/block, thread per (bin, 16B chunk),
// 4-edge unroll, direct __ldg idx loads. Gather reads the fp16 mirror
// (half the sectors per edge); combine/own-x stay fp32. Output written to
// both fp32 buffer and fp16 mirror.
template <int INS, int OUTS>
__global__ __launch_bounds__(256)
void k_layer(int inA, int layer,
             const float* __restrict__ root, const float* __restrict__ bias,
             int do_relu) {
    const int CH  = INS / 4;             // fp32 float4 chunks (combine path)
    const int CHH = INS / 8;             // fp16 16B chunks (gather path)
    const int NODES = 128, BINS = 256;
    const int APAD = 2 * INS + 2;
    __shared__ float sA[NODES * APAD];
    __shared__ alignas(16) float sR[INS * OUTS];
    __shared__ alignas(16) float sW0[INS * OUTS];
    __shared__ alignas(16) float sW1[INS * OUTS];
    __shared__ float sb[OUTS];

    int tid = threadIdx.x;
    const float* W0g = g_Wall + layer * 2048;
    const float* W1g = W0g + 1024;
    for (int i = tid; i < INS * OUTS; i += 256) {
        sR[i]  = __ldg(&root[i]);
        sW0[i] = W0g[i];
        sW1[i] = W1g[i];
    }
    if (tid < OUTS) sb[tid] = __ldg(&bias[tid]);

    int nodeBase = blockIdx.x * NODES;
    int bin0 = nodeBase * 2;
    const float4* __restrict__ xin = inA ? g_bufA4 : g_bufB4;
    const uint4*  __restrict__ hin = (const uint4*)(inA ? g_hA : g_hB);
    float* __restrict__ xout = inA ? (float*)g_bufB4 : (float*)g_bufA4;
    __half* __restrict__ hout = inA ? g_hB : g_hA;

    // ---- gather phase: thread per (bin, 16B fp16 chunk = 8 features) ----
    for (int u = tid; u < BINS * CHH; u += 256) {
        int bl = u / CHH, c = u % CHH;
        int w = bin0 + bl;
        float s0[8], s1[8];
#pragma unroll
        for (int k = 0; k < 8; k++) { s0[k] = 0.f; s1[k] = 0.f; }
        int cnt = 0;
        if (w < NBINS) {
            int start = __ldg(&g_off[w]);
            cnt = __ldg(&g_off[w + 1]) - start;
            const int* ep = g_esrc + start;
            int i = 0;
            for (; i + 4 <= cnt; i += 4) {
                int a = __ldg(ep + i), b2 = __ldg(ep + i + 1);
                int d = __ldg(ep + i + 2), e = __ldg(ep + i + 3);
                uint4 va = __ldg(hin + a * CHH + c);
                uint4 vb = __ldg(hin + b2 * CHH + c);
                uint4 vd = __ldg(hin + d * CHH + c);
                uint4 ve = __ldg(hin + e * CHH + c);
                const __half2* ha = (const __half2*)&va;
                const __half2* hb = (const __half2*)&vb;
                const __half2* hd = (const __half2*)&vd;
                const __half2* he = (const __half2*)&ve;
#pragma unroll
                for (int k = 0; k < 4; k++) {
                    float2 fa = __half22float2(ha[k]);
                    float2 fb = __half22float2(hb[k]);
                    float2 fd = __half22float2(hd[k]);
                    float2 fe = __half22float2(he[k]);
                    s0[k*2]   += fa.x + fd.x;
                    s0[k*2+1] += fa.y + fd.y;
                    s1[k*2]   += fb.x + fe.x;
                    s1[k*2+1] += fb.y + fe.y;
                }
            }
            for (; i < cnt; i++) {
                int a = __ldg(ep + i);
                uint4 va = __ldg(hin + a * CHH + c);
                const __half2* ha = (const __half2*)&va;
#pragma unroll
                for (int k = 0; k < 4; k++) {
                    float2 fa = __half22float2(ha[k]);
                    s0[k*2]   += fa.x;
                    s0[k*2+1] += fa.y;
                }
            }
        }
        float inv = cnt > 0 ? 1.0f / (float)cnt : 0.0f;
        int node = bl >> 1, rel = bl & 1;
        int b = node * APAD + rel * INS + c * 8;
#pragma unroll
        for (int k = 0; k < 8; k++) sA[b + k] = (s0[k] + s1[k]) * inv;
    }
    __syncthreads();

    // ---- combine phase: 2 nodes/thread, q-th output quarter (fp32) ----
    const int OQ = OUTS / 4;
    int g = tid >> 2;
    int q = tid & 3;
    int o0 = q * OQ;
    int ln0 = g * 2;
    int gn0 = nodeBase + ln0;
    const float* A0 = sA + ln0 * APAD;
    const float* A1 = A0 + APAD;

    float acc0[OQ], acc1[OQ];
#pragma unroll
    for (int j = 0; j < OQ; j++) { acc0[j] = sb[o0 + j]; acc1[j] = sb[o0 + j]; }

#pragma unroll
    for (int i4 = 0; i4 < CH; i4++) {
        float4 x0 = (gn0 < NN) ? __ldg(xin + gn0 * CH + i4)
                               : make_float4(0.f, 0.f, 0.f, 0.f);
        float4 x1 = (gn0 + 1 < NN) ? __ldg(xin + (gn0 + 1) * CH + i4)
                                   : make_float4(0.f, 0.f, 0.f, 0.f);
        const float* xs0 = (const float*)&x0;
        const float* xs1 = (const float*)&x1;
#pragma unroll
        for (int j = 0; j < 4; j++) {
            int i = i4 * 4 + j;
            float xv0 = xs0[j], xv1 = xs1[j];
            float a00 = A0[i], a01 = A0[INS + i];
            float a10 = A1[i], a11 = A1[INS + i];
            const float4* r4  = (const float4*)&sR[i * OUTS + o0];
            const float4* w04 = (const float4*)&sW0[i * OUTS + o0];
            const float4* w14 = (const float4*)&sW1[i * OUTS + o0];
#pragma unroll
            for (int j4 = 0; j4 < OQ / 4; j4++) {
                float4 r = r4[j4], w0 = w04[j4], w1 = w14[j4];
                acc0[j4*4+0] += xv0 * r.x + a00 * w0.x + a01 * w1.x;
                acc0[j4*4+1] += xv0 * r.y + a00 * w0.y + a01 * w1.y;
                acc0[j4*4+2] += xv0 * r.z + a00 * w0.z + a01 * w1.z;
                acc0[j4*4+3] += xv0 * r.w + a00 * w0.w + a01 * w1.w;
                acc1[j4*4+0] += xv1 * r.x + a10 * w0.x + a11 * w1.x;
                acc1[j4*4+1] += xv1 * r.y + a10 * w0.y + a11 * w1.y;
                acc1[j4*4+2] += xv1 * r.z + a10 * w0.z + a11 * w1.z;
                acc1[j4*4+3] += xv1 * r.w + a10 * w0.w + a11 * w1.w;
            }
        }
    }
    if (do_relu) {
#pragma unroll
        for (int j = 0; j < OQ; j++) {
            acc0[j] = fmaxf(acc0[j], 0.f);
            acc1[j] = fmaxf(acc1[j], 0.f);
        }
    }
#pragma unroll
    for (int j4 = 0; j4 < OQ / 4; j4++) {
        if (gn0 < NN)
            ((float4*)xout)[gn0 * (OUTS / 4) + q * (OQ / 4) + j4] =
                make_float4(acc0[j4*4+0], acc0[j4*4+1], acc0[j4*4+2], acc0[j4*4+3]);
        if (gn0 + 1 < NN)
            ((float4*)xout)[(gn0 + 1) * (OUTS / 4) + q * (OQ / 4) + j4] =
                make_float4(acc1[j4*4+0], acc1[j4*4+1], acc1[j4*4+2], acc1[j4*4+3]);
    }
    // fp16 mirrors: OQ halves per node at half-offset gn*OUTS + o0
    {
        __half2 h0[OQ / 2], h1[OQ / 2];
#pragma unroll
        for (int j2 = 0; j2 < OQ / 2; j2++) {
            h0[j2] = __floats2half2_rn(acc0[j2 * 2], acc0[j2 * 2 + 1]);
            h1[j2] = __floats2half2_rn(acc1[j2 * 2], acc1[j2 * 2 + 1]);
        }
        if (gn0 < NN) {
            __half2* dst = (__half2*)(hout + gn0 * OUTS + o0);
#pragma unroll
            for (int j2 = 0; j2 < OQ / 2; j2++) dst[j2] = h0[j2];
        }
        if (gn0 + 1 < NN) {
            __half2* dst = (__half2*)(hout + (gn0 + 1) * OUTS + o0);
#pragma unroll
            for (int j2 = 0; j2 < OQ / 2; j2++) dst[j2] = h1[j2];
        }
    }
}

// ---------------- decoder ----------------------------------------------------
__global__ void k_decode(const int* __restrict__ pei, const int* __restrict__ pet,
                         const int* __restrict__ nei, const int* __restrict__ net,
                         const float* __restrict__ Wd0, const float* __restrict__ bd0,
                         const float* __restrict__ Wd1, const float* __restrict__ bd1,
                         float* __restrict__ out) {
    __shared__ float sW0[256], sW1[256], sb0[16], sb1[16];
    int tid = threadIdx.x;
    if (tid < 256) { sW0[tid] = Wd0[tid]; sW1[tid] = Wd1[tid]; }
    if (tid < 16) { sb0[tid] = bd0[tid]; sb1[tid] = bd1[tid]; }
    __syncthreads();
    int g = blockIdx.x * blockDim.x + tid;
    int e = g >> 4;
    int c = g & 15;
    if (e >= 2 * EDC) return;
    const int* ei;
    const int* et;
    int le;
    float* o;
    if (e < EDC) { ei = pei; et = pet; le = e; o = out; }
    else         { ei = nei; et = net; le = e - EDC; o = out + EDC; }
    const float* z = (const float*)g_bufA4;
    int src = __ldg(&ei[le]);
    int dst = __ldg(&ei[EDC + le]);
    int t = __ldg(&et[le]);
    float zs = __ldg(&z[src * 16 + c]);
    float zd = __ldg(&z[dst * 16 + c]);
    const float* W = (t == 0) ? sW0 : sW1;
    float h = (t == 0) ? sb0[c] : sb1[c];
#pragma unroll
    for (int i = 0; i < 16; i++) {
        float zi = __shfl_sync(0xffffffffu, zs, i, 16);
        h += zi * W[i * 16 + c];
    }
    float p = h * zd;
#pragma unroll
    for (int off = 8; off >= 1; off >>= 1)
        p += __shfl_down_sync(0xffffffffu, p, off, 16);
    if (c == 0) o[le] = p;
}

// ---------------- launch -----------------------------------------------------
extern "C" void kernel_launch(void* const* d_in, const int* in_sizes, int n_in,
                              void* d_out, int out_size) {
    const float* xp   = (const float*)d_in[0];
    const float* xm   = (const float*)d_in[1];
    const int*   tei  = (const int*)d_in[2];
    const int*   tet  = (const int*)d_in[3];
    const int*   pei  = (const int*)d_in[4];
    const int*   pet  = (const int*)d_in[5];
    const int*   nei  = (const int*)d_in[6];
    const int*   net_ = (const int*)d_in[7];
    const float* Wp   = (const float*)d_in[8];
    const float* bp   = (const float*)d_in[9];
    const float* Wm   = (const float*)d_in[10];
    const float* bm   = (const float*)d_in[11];
    const float* Wd0  = (const float*)d_in[12];
    const float* bd0  = (const float*)d_in[13];
    const float* Wd1  = (const float*)d_in[14];
    const float* bd1  = (const float*)d_in[15];
    const float* bases[4] = {(const float*)d_in[16], (const float*)d_in[20],
                             (const float*)d_in[24], (const float*)d_in[28]};
    const float* comp[4]  = {(const float*)d_in[17], (const float*)d_in[21],
                             (const float*)d_in[25], (const float*)d_in[29]};
    const float* root[4]  = {(const float*)d_in[18], (const float*)d_in[22],
                             (const float*)d_in[26], (const float*)d_in[30]};
    const float* bias[4]  = {(const float*)d_in[19], (const float*)d_in[23],
                             (const float*)d_in[27], (const float*)d_in[31]};
    float* out = (float*)d_out;

    const int TB = 256;
    // 1: hist, 2: scanLB, 3: fused front, 4: layer1 (PROFILED SLOT), 5-7: layers, 8: decode
    k_hist<<<(ETR / 8 + TB - 1) / TB, TB>>>(tei, tet);
    k_scanLB<<<NBLK, 256>>>();
    k_scatter_front<<<SCBLK + TFBLK + PCBLK + ZBLK, 256>>>(
        tei, tet, xp, xm, Wp, bp, Wm, bm,
        bases[0], comp[0], bases[1], comp[1],
        bases[2], comp[2], bases[3], comp[3]);

    const int LBLK = (NN + 127) / 128;   // 704
    k_layer<16, 32><<<LBLK, 256>>>(1, 0, root[0], bias[0], 1);
    k_layer<32, 32><<<LBLK, 256>>>(0, 1, root[1], bias[1], 1);
    k_layer<32, 32><<<LBLK, 256>>>(1, 2, root[2], bias[2], 1);
    k_layer<32, 16><<<LBLK, 256>>>(0, 3, root[3], bias[3], 0);

    k_decode<<<(2 * EDC * 16 + TB - 1) / TB, TB>>>(pei, pet, nei, net_,
                                                   Wd0, bd0, Wd1, bd1, out);
}

// round 17
// speedup vs baseline: 1.4597x; 1.0307x over previous
#include <cuda_runtime.h>
#include <cuda_fp16.h>

#define NP 60000
#define NM 30000
#define NN 90000
#define ETR 2000000
#define EDC 400000
#define NBINS (2*NN)
#define NBLK 176                         // scan blocks (176*1024 >= NBINS)
#define SCBLK ((ETR/8 + 255) / 256)      // 977 scatter blocks
#define TFBLK ((NN + 255) / 256)         // 352 transform blocks
#define PCBLK 24                         // precomp blocks
#define ZBLK  176                        // zero blocks

// ---------------- device scratch ---------------------------------------------
__device__ float4 g_bufA4[NN * 8];
__device__ float4 g_bufB4[NN * 8];
__device__ __align__(16) __half g_hA[NN * 32];   // fp16 mirrors (gather path)
__device__ __align__(16) __half g_hB[NN * 32];
__device__ int    g_cnt[NBINS];
__device__ int    g_off[NBINS + 1];
__device__ int    g_cur[NBINS];
__device__ int    g_esrc[ETR];
__device__ float  g_Wall[4 * 2048];
__device__ volatile int g_blkAgg[NBLK];
__device__ volatile int g_blkFlag[NBLK];

// ---------------- hist -------------------------------------------------------
__global__ void k_hist(const int* __restrict__ ei, const int* __restrict__ et) {
    int t = blockIdx.x * blockDim.x + threadIdx.x;
    int e = t * 8;
    if (e >= ETR) return;
    int4 d0 = *(const int4*)&ei[ETR + e];
    int4 d1 = *(const int4*)&ei[ETR + e + 4];
    int4 r0 = *(const int4*)&et[e];
    int4 r1 = *(const int4*)&et[e + 4];
    atomicAdd(&g_cnt[d0.x * 2 + r0.x], 1);
    atomicAdd(&g_cnt[d0.y * 2 + r0.y], 1);
    atomicAdd(&g_cnt[d0.z * 2 + r0.z], 1);
    atomicAdd(&g_cnt[d0.w * 2 + r0.w], 1);
    atomicAdd(&g_cnt[d1.x * 2 + r1.x], 1);
    atomicAdd(&g_cnt[d1.y * 2 + r1.y], 1);
    atomicAdd(&g_cnt[d1.z * 2 + r1.z], 1);
    atomicAdd(&g_cnt[d1.w * 2 + r1.w], 1);
}

// ---------------- single-pass scan with decoupled lookback -------------------
__global__ __launch_bounds__(256)
void k_scanLB() {
    __shared__ int sh[256];
    int b = blockIdx.x, t = threadIdx.x;
    int base = b * 1024 + t * 4;
    int4 v = make_int4(0, 0, 0, 0);
    if (base < NBINS) v = *(const int4*)&g_cnt[base];
    int s = v.x + v.y + v.z + v.w;
    sh[t] = s;
    __syncthreads();
    for (int off = 1; off < 256; off <<= 1) {
        int tmp = (t >= off) ? sh[t - off] : 0;
        __syncthreads();
        sh[t] += tmp;
        __syncthreads();
    }
    int myinc = sh[t];
    if (t == 255) {
        g_blkAgg[b] = myinc;
        __threadfence();
        g_blkFlag[b] = 1;
    }
    int prev = 0;
    for (int j = t; j < b; j += 256) {
        while (g_blkFlag[j] == 0) { }
        prev += g_blkAgg[j];
    }
    __syncthreads();
    sh[t] = prev;
    __syncthreads();
    for (int off = 128; off >= 1; off >>= 1) {
        if (t < off) sh[t] += sh[t + off];
        __syncthreads();
    }
    int blkoff = sh[0];
    if (base < NBINS) {
        int run = myinc - s + blkoff;
        int4 o;
        o.x = run;           run += v.x;
        o.y = run;           run += v.y;
        o.z = run;           run += v.z;
        o.w = run;
        *(int4*)&g_off[base] = o;
        *(int4*)&g_cur[base] = o;
    }
    if (b == 0 && t == 0) g_off[NBINS] = ETR;
}

// ------- fused: scatter + input transform + basis precomp + state reset ------
__global__ __launch_bounds__(256)
void k_scatter_front(const int* __restrict__ ei, const int* __restrict__ et,
                     const float* __restrict__ xp, const float* __restrict__ xm,
                     const float* __restrict__ Wp, const float* __restrict__ bp,
                     const float* __restrict__ Wm, const float* __restrict__ bm,
                     const float* __restrict__ b1, const float* __restrict__ c1,
                     const float* __restrict__ b2, const float* __restrict__ c2,
                     const float* __restrict__ b3, const float* __restrict__ c3,
                     const float* __restrict__ b4, const float* __restrict__ c4) {
    int bx = blockIdx.x;
    int t = threadIdx.x;

    if (bx < SCBLK) {
        int e = (bx * 256 + t) * 8;
        if (e >= ETR) return;
        int4 s0 = *(const int4*)&ei[e];
        int4 s1 = *(const int4*)&ei[e + 4];
        int4 d0 = *(const int4*)&ei[ETR + e];
        int4 d1 = *(const int4*)&ei[ETR + e + 4];
        int4 r0 = *(const int4*)&et[e];
        int4 r1 = *(const int4*)&et[e + 4];
        int p0 = atomicAdd(&g_cur[d0.x * 2 + r0.x], 1);
        int p1 = atomicAdd(&g_cur[d0.y * 2 + r0.y], 1);
        int p2 = atomicAdd(&g_cur[d0.z * 2 + r0.z], 1);
        int p3 = atomicAdd(&g_cur[d0.w * 2 + r0.w], 1);
        int p4 = atomicAdd(&g_cur[d1.x * 2 + r1.x], 1);
        int p5 = atomicAdd(&g_cur[d1.y * 2 + r1.y], 1);
        int p6 = atomicAdd(&g_cur[d1.z * 2 + r1.z], 1);
        int p7 = atomicAdd(&g_cur[d1.w * 2 + r1.w], 1);
        g_esrc[p0] = s0.x; g_esrc[p1] = s0.y; g_esrc[p2] = s0.z; g_esrc[p3] = s0.w;
        g_esrc[p4] = s1.x; g_esrc[p5] = s1.y; g_esrc[p6] = s1.z; g_esrc[p7] = s1.w;
        return;
    }
    if (bx < SCBLK + TFBLK) {
        __shared__ float4 sWp[512], sWm[512];
        __shared__ float  sbp[16], sbm[16];
        for (int i = t; i < 512; i += 256) {
            sWp[i] = __ldg((const float4*)Wp + i);
            sWm[i] = __ldg((const float4*)Wm + i);
        }
        if (t < 16) { sbp[t] = __ldg(&bp[t]); sbm[t] = __ldg(&bm[t]); }
        __syncthreads();

        int n = (bx - SCBLK) * 256 + t;
        if (n >= NN) return;
        bool paper = (n < NP);
        const float4* xb = paper ? ((const float4*)xp + (long)n * 32)
                                 : ((const float4*)xm + (long)(n - NP) * 32);
        const float4* W  = paper ? sWp : sWm;
        const float*  sb = paper ? sbp : sbm;

        float acc[16];
#pragma unroll
        for (int o = 0; o < 16; o++) acc[o] = sb[o];
#pragma unroll
        for (int k8 = 0; k8 < 4; k8++) {
            float4 xv[8];
#pragma unroll
            for (int m = 0; m < 8; m++) xv[m] = __ldg(xb + k8 * 8 + m);
#pragma unroll
            for (int m = 0; m < 8; m++) {
                const float* xs = (const float*)&xv[m];
#pragma unroll
                for (int j = 0; j < 4; j++) {
                    int k = k8 * 32 + m * 4 + j;
                    float x = xs[j];
#pragma unroll
                    for (int o4 = 0; o4 < 4; o4++) {
                        float4 wv = W[k * 4 + o4];
                        acc[o4*4+0] += x * wv.x;
                        acc[o4*4+1] += x * wv.y;
                        acc[o4*4+2] += x * wv.z;
                        acc[o4*4+3] += x * wv.w;
                    }
                }
            }
        }
#pragma unroll
        for (int o4 = 0; o4 < 4; o4++)
            g_bufA4[n * 4 + o4] = make_float4(acc[o4*4+0], acc[o4*4+1],
                                              acc[o4*4+2], acc[o4*4+3]);
        // fp16 mirror (row = 16 halves = 32B)
        {
            uint4 hv[2];
            __half2* hp = (__half2*)hv;
#pragma unroll
            for (int o2 = 0; o2 < 8; o2++)
                hp[o2] = __floats2half2_rn(acc[o2 * 2], acc[o2 * 2 + 1]);
            ((uint4*)g_hA)[n * 2 + 0] = hv[0];
            ((uint4*)g_hA)[n * 2 + 1] = hv[1];
        }
        return;
    }
    if (bx < SCBLK + TFBLK + PCBLK) {
        int tid = (bx - SCBLK - TFBLK) * 256 + t;
        const int sizes[4] = {512, 1024, 1024, 512};
        const float* bases[4] = {b1, b2, b3, b4};
        const float* comp[4]  = {c1, c2, c3, c4};
        if (tid >= 6144) return;
        int rem = tid;
        int l = 0;
        while (rem >= 2 * sizes[l]) { rem -= 2 * sizes[l]; l++; }
        int sz = sizes[l];
        int r = rem / sz;
        int io = rem - r * sz;
        float s = 0.f;
#pragma unroll
        for (int b = 0; b < 4; b++)
            s += __ldg(&comp[l][r * 4 + b]) * __ldg(&bases[l][b * sz + io]);
        g_Wall[l * 2048 + r * 1024 + io] = s;
        return;
    }
    {
        int zb = bx - SCBLK - TFBLK - PCBLK;
        int i = zb * 256 + t;
        if (i < NBINS / 4) *(int4*)&g_cnt[i * 4] = make_int4(0, 0, 0, 0);
        if (zb == 0 && t < NBLK) { g_blkFlag[t] = 0; g_blkAgg[t] = 0; }
    }
}

// ---------------- fused layer: gather-mean (fp16 rows) + combine (fp32) ------
// 128 nodes/block. Gather: thread per (bin, 32B half-row) -> idx loaded once
// per TPB (=INS/16) threads, 2 independent LDG.128 feature loads per edge.
// Combine fp32 as before; outputs written to fp32 buffer + fp16 mirror.
template <int INS, int OUTS>
__global__ __launch_bounds__(256)
void k_layer(int inA, int layer,
             const float* __restrict__ root, const float* __restrict__ bias,
             int do_relu) {
    const int CH  = INS / 4;             // fp32 float4 chunks (combine path)
    const int CHH = INS / 8;             // fp16 16B chunks per row
    const int TPB = INS / 16;            // gather threads per bin (1 or 2)
    const int NODES = 128, BINS = 256;
    const int APAD = 2 * INS + 2;
    __shared__ float sA[NODES * APAD];
    __shared__ alignas(16) float sR[INS * OUTS];
    __shared__ alignas(16) float sW0[INS * OUTS];
    __shared__ alignas(16) float sW1[INS * OUTS];
    __shared__ float sb[OUTS];

    int tid = threadIdx.x;
    const float* W0g = g_Wall + layer * 2048;
    const float* W1g = W0g + 1024;
    for (int i = tid; i < INS * OUTS; i += 256) {
        sR[i]  = __ldg(&root[i]);
        sW0[i] = W0g[i];
        sW1[i] = W1g[i];
    }
    if (tid < OUTS) sb[tid] = __ldg(&bias[tid]);

    int nodeBase = blockIdx.x * NODES;
    int bin0 = nodeBase * 2;
    const float4* __restrict__ xin = inA ? g_bufA4 : g_bufB4;
    const uint4*  __restrict__ hin = (const uint4*)(inA ? g_hA : g_hB);
    float* __restrict__ xout = inA ? (float*)g_bufB4 : (float*)g_bufA4;
    __half* __restrict__ hout = inA ? g_hB : g_hA;

    // ---- gather phase: thread per (bin, 32B half-row = 16 features) ----
    for (int u = tid; u < BINS * TPB; u += 256) {
        int bl = u / TPB, cp = u % TPB;  // cp-th 32B half-row
        int w = bin0 + bl;
        float s[16];
#pragma unroll
        for (int k = 0; k < 16; k++) s[k] = 0.f;
        int cnt = 0;
        if (w < NBINS) {
            int start = __ldg(&g_off[w]);
            cnt = __ldg(&g_off[w + 1]) - start;
            const int* ep = g_esrc + start;
            int i = 0;
            for (; i + 4 <= cnt; i += 4) {
                int a  = __ldg(ep + i),     b2 = __ldg(ep + i + 1);
                int d  = __ldg(ep + i + 2), e  = __ldg(ep + i + 3);
                uint4 va0 = __ldg(hin + a  * CHH + cp * 2);
                uint4 va1 = __ldg(hin + a  * CHH + cp * 2 + 1);
                uint4 vb0 = __ldg(hin + b2 * CHH + cp * 2);
                uint4 vb1 = __ldg(hin + b2 * CHH + cp * 2 + 1);
                uint4 vd0 = __ldg(hin + d  * CHH + cp * 2);
                uint4 vd1 = __ldg(hin + d  * CHH + cp * 2 + 1);
                uint4 ve0 = __ldg(hin + e  * CHH + cp * 2);
                uint4 ve1 = __ldg(hin + e  * CHH + cp * 2 + 1);
                const __half2* h;
#pragma unroll
                for (int k = 0; k < 4; k++) {
                    float2 f;
                    h = (const __half2*)&va0; f = __half22float2(h[k]); s[k*2] += f.x; s[k*2+1] += f.y;
                    h = (const __half2*)&vb0; f = __half22float2(h[k]); s[k*2] += f.x; s[k*2+1] += f.y;
                    h = (const __half2*)&vd0; f = __half22float2(h[k]); s[k*2] += f.x; s[k*2+1] += f.y;
                    h = (const __half2*)&ve0; f = __half22float2(h[k]); s[k*2] += f.x; s[k*2+1] += f.y;
                    h = (const __half2*)&va1; f = __half22float2(h[k]); s[8+k*2] += f.x; s[8+k*2+1] += f.y;
                    h = (const __half2*)&vb1; f = __half22float2(h[k]); s[8+k*2] += f.x; s[8+k*2+1] += f.y;
                    h = (const __half2*)&vd1; f = __half22float2(h[k]); s[8+k*2] += f.x; s[8+k*2+1] += f.y;
                    h = (const __half2*)&ve1; f = __half22float2(h[k]); s[8+k*2] += f.x; s[8+k*2+1] += f.y;
                }
            }
            for (; i < cnt; i++) {
                int a = __ldg(ep + i);
                uint4 v0 = __ldg(hin + a * CHH + cp * 2);
                uint4 v1 = __ldg(hin + a * CHH + cp * 2 + 1);
                const __half2* h0 = (const __half2*)&v0;
                const __half2* h1 = (const __half2*)&v1;
#pragma unroll
                for (int k = 0; k < 4; k++) {
                    float2 f0 = __half22float2(h0[k]);
                    float2 f1 = __half22float2(h1[k]);
                    s[k*2]     += f0.x; s[k*2+1]   += f0.y;
                    s[8+k*2]   += f1.x; s[8+k*2+1] += f1.y;
                }
            }
        }
        float inv = cnt > 0 ? 1.0f / (float)cnt : 0.0f;
        int node = bl >> 1, rel = bl & 1;
        int b = node * APAD + rel * INS + cp * 16;
#pragma unroll
        for (int k = 0; k < 16; k++) sA[b + k] = s[k] * inv;
    }
    __syncthreads();

    // ---- combine phase: 2 nodes/thread, q-th output quarter (fp32) ----
    const int OQ = OUTS / 4;
    int g = tid >> 2;
    int q = tid & 3;
    int o0 = q * OQ;
    int ln0 = g * 2;
    int gn0 = nodeBase + ln0;
    const float* A0 = sA + ln0 * APAD;
    const float* A1 = A0 + APAD;

    float acc0[OQ], acc1[OQ];
#pragma unroll
    for (int j = 0; j < OQ; j++) { acc0[j] = sb[o0 + j]; acc1[j] = sb[o0 + j]; }

#pragma unroll
    for (int i4 = 0; i4 < CH; i4++) {
        float4 x0 = (gn0 < NN) ? __ldg(xin + gn0 * CH + i4)
                               : make_float4(0.f, 0.f, 0.f, 0.f);
        float4 x1 = (gn0 + 1 < NN) ? __ldg(xin + (gn0 + 1) * CH + i4)
                                   : make_float4(0.f, 0.f, 0.f, 0.f);
        const float* xs0 = (const float*)&x0;
        const float* xs1 = (const float*)&x1;
#pragma unroll
        for (int j = 0; j < 4; j++) {
            int i = i4 * 4 + j;
            float xv0 = xs0[j], xv1 = xs1[j];
            float a00 = A0[i], a01 = A0[INS + i];
            float a10 = A1[i], a11 = A1[INS + i];
            const float4* r4  = (const float4*)&sR[i * OUTS + o0];
            const float4* w04 = (const float4*)&sW0[i * OUTS + o0];
            const float4* w14 = (const float4*)&sW1[i * OUTS + o0];
#pragma unroll
            for (int j4 = 0; j4 < OQ / 4; j4++) {
                float4 r = r4[j4], w0 = w04[j4], w1 = w14[j4];
                acc0[j4*4+0] += xv0 * r.x + a00 * w0.x + a01 * w1.x;
                acc0[j4*4+1] += xv0 * r.y + a00 * w0.y + a01 * w1.y;
                acc0[j4*4+2] += xv0 * r.z + a00 * w0.z + a01 * w1.z;
                acc0[j4*4+3] += xv0 * r.w + a00 * w0.w + a01 * w1.w;
                acc1[j4*4+0] += xv1 * r.x + a10 * w0.x + a11 * w1.x;
                acc1[j4*4+1] += xv1 * r.y + a10 * w0.y + a11 * w1.y;
                acc1[j4*4+2] += xv1 * r.z + a10 * w0.z + a11 * w1.z;
                acc1[j4*4+3] += xv1 * r.w + a10 * w0.w + a11 * w1.w;
            }
        }
    }
    if (do_relu) {
#pragma unroll
        for (int j = 0; j < OQ; j++) {
            acc0[j] = fmaxf(acc0[j], 0.f);
            acc1[j] = fmaxf(acc1[j], 0.f);
        }
    }
#pragma unroll
    for (int j4 = 0; j4 < OQ / 4; j4++) {
        if (gn0 < NN)
            ((float4*)xout)[gn0 * (OUTS / 4) + q * (OQ / 4) + j4] =
                make_float4(acc0[j4*4+0], acc0[j4*4+1], acc0[j4*4+2], acc0[j4*4+3]);
        if (gn0 + 1 < NN)
            ((float4*)xout)[(gn0 + 1) * (OUTS / 4) + q * (OQ / 4) + j4] =
                make_float4(acc1[j4*4+0], acc1[j4*4+1], acc1[j4*4+2], acc1[j4*4+3]);
    }
    // fp16 mirrors
    {
        __half2 h0[OQ / 2], h1[OQ / 2];
#pragma unroll
        for (int j2 = 0; j2 < OQ / 2; j2++) {
            h0[j2] = __floats2half2_rn(acc0[j2 * 2], acc0[j2 * 2 + 1]);
            h1[j2] = __floats2half2_rn(acc1[j2 * 2], acc1[j2 * 2 + 1]);
        }
        if (gn0 < NN) {
            __half2* dst = (__half2*)(hout + gn0 * OUTS + o0);
#pragma unroll
            for (int j2 = 0; j2 < OQ / 2; j2++) dst[j2] = h0[j2];
        }
        if (gn0 + 1 < NN) {
            __half2* dst = (__half2*)(hout + (gn0 + 1) * OUTS + o0);
#pragma unroll
            for (int j2 = 0; j2 < OQ / 2; j2++) dst[j2] = h1[j2];
        }
    }
}

// ---------------- decoder ----------------------------------------------------
__global__ void k_decode(const int* __restrict__ pei, const int* __restrict__ pet,
                         const int* __restrict__ nei, const int* __restrict__ net,
                         const float* __restrict__ Wd0, const float* __restrict__ bd0,
                         const float* __restrict__ Wd1, const float* __restrict__ bd1,
                         float* __restrict__ out) {
    __shared__ float sW0[256], sW1[256], sb0[16], sb1[16];
    int tid = threadIdx.x;
    if (tid < 256) { sW0[tid] = Wd0[tid]; sW1[tid] = Wd1[tid]; }
    if (tid < 16) { sb0[tid] = bd0[tid]; sb1[tid] = bd1[tid]; }
    __syncthreads();
    int g = blockIdx.x * blockDim.x + tid;
    int e = g >> 4;
    int c = g & 15;
    if (e >= 2 * EDC) return;
    const int* ei;
    const int* et;
    int le;
    float* o;
    if (e < EDC) { ei = pei; et = pet; le = e; o = out; }
    else         { ei = nei; et = net; le = e - EDC; o = out + EDC; }
    const float* z = (const float*)g_bufA4;
    int src = __ldg(&ei[le]);
    int dst = __ldg(&ei[EDC + le]);
    int t = __ldg(&et[le]);
    float zs = __ldg(&z[src * 16 + c]);
    float zd = __ldg(&z[dst * 16 + c]);
    const float* W = (t == 0) ? sW0 : sW1;
    float h = (t == 0) ? sb0[c] : sb1[c];
#pragma unroll
    for (int i = 0; i < 16; i++) {
        float zi = __shfl_sync(0xffffffffu, zs, i, 16);
        h += zi * W[i * 16 + c];
    }
    float p = h * zd;
#pragma unroll
    for (int off = 8; off >= 1; off >>= 1)
        p += __shfl_down_sync(0xffffffffu, p, off, 16);
    if (c == 0) o[le] = p;
}

// ---------------- launch -----------------------------------------------------
extern "C" void kernel_launch(void* const* d_in, const int* in_sizes, int n_in,
                              void* d_out, int out_size) {
    const float* xp   = (const float*)d_in[0];
    const float* xm   = (const float*)d_in[1];
    const int*   tei  = (const int*)d_in[2];
    const int*   tet  = (const int*)d_in[3];
    const int*   pei  = (const int*)d_in[4];
    const int*   pet  = (const int*)d_in[5];
    const int*   nei  = (const int*)d_in[6];
    const int*   net_ = (const int*)d_in[7];
    const float* Wp   = (const float*)d_in[8];
    const float* bp   = (const float*)d_in[9];
    const float* Wm   = (const float*)d_in[10];
    const float* bm   = (const float*)d_in[11];
    const float* Wd0  = (const float*)d_in[12];
    const float* bd0  = (const float*)d_in[13];
    const float* Wd1  = (const float*)d_in[14];
    const float* bd1  = (const float*)d_in[15];
    const float* bases[4] = {(const float*)d_in[16], (const float*)d_in[20],
                             (const float*)d_in[24], (const float*)d_in[28]};
    const float* comp[4]  = {(const float*)d_in[17], (const float*)d_in[21],
                             (const float*)d_in[25], (const float*)d_in[29]};
    const float* root[4]  = {(const float*)d_in[18], (const float*)d_in[22],
                             (const float*)d_in[26], (const float*)d_in[30]};
    const float* bias[4]  = {(const float*)d_in[19], (const float*)d_in[23],
                             (const float*)d_in[27], (const float*)d_in[31]};
    float* out = (float*)d_out;

    const int TB = 256;
    // 1: hist, 2: scanLB, 3: fused front, 4: layer1 (PROFILED SLOT), 5-7: layers, 8: decode
    k_hist<<<(ETR / 8 + TB - 1) / TB, TB>>>(tei, tet);
    k_scanLB<<<NBLK, 256>>>();
    k_scatter_front<<<SCBLK + TFBLK + PCBLK + ZBLK, 256>>>(
        tei, tet, xp, xm, Wp, bp, Wm, bm,
        bases[0], comp[0], bases[1], comp[1],
        bases[2], comp[2], bases[3], comp[3]);

    const int LBLK = (NN + 127) / 128;   // 704
    k_layer<16, 32><<<LBLK, 256>>>(1, 0, root[0], bias[0], 1);
    k_layer<32, 32><<<LBLK, 256>>>(0, 1, root[1], bias[1], 1);
    k_layer<32, 32><<<LBLK, 256>>>(1, 2, root[2], bias[2], 1);
    k_layer<32, 16><<<LBLK, 256>>>(0, 3, root[3], bias[3], 0);

    k_decode<<<(2 * EDC * 16 + TB - 1) / TB, TB>>>(pei, pet, nei, net_,
                                                   Wd0, bd0, Wd1, bd1, out);
}